// round 1
// baseline (speedup 1.0000x reference)
#include <cuda_runtime.h>
#include <math.h>

// Problem constants
#define Tt 200
#define Bb 512
#define Cc 128
#define Hh 4
#define Kk 5
#define Ff 512
#define Ll 2
#define BTt (Tt*Bb)        // 102400 tokens
#define HK  (Hh*Kk)        // 20
#define NPART (BTt/8)      // 12800 partial sums (one per block of 8 warps)

// Scratch (static device allocations — allowed)
__device__ float g_X  [BTt*Cc];   // activations, layout [t*B+b][c]
__device__ float g_XLN[BTt*Cc];   // layernormed activations / residual base
__device__ float g_Y  [BTt*Cc];   // conv output
__device__ float g_H  [BTt*Ff];   // FFN hidden
__device__ float g_pL [NPART];
__device__ float g_pM [NPART];

// ---------------------------------------------------------------------------
// Embedding gather: X[t*B+b][:] = item_emb[seq[b][t]][:]
// warp per token, float4 per lane (32*4 = 128 ch)
// ---------------------------------------------------------------------------
__global__ void embed_kernel(const float* __restrict__ emb,
                             const int* __restrict__ seq,
                             float* __restrict__ X)
{
    int warp = threadIdx.x >> 5, lane = threadIdx.x & 31;
    int p = blockIdx.x * 8 + warp;
    int t = p / Bb, b = p - t * Bb;
    int id = seq[b * Tt + t];
    float4 v = ((const float4*)(emb + (size_t)id * Cc))[lane];
    ((float4*)(X + (size_t)p * Cc))[lane] = v;
}

// ---------------------------------------------------------------------------
// LayerNorm over C=128, warp per token
// ---------------------------------------------------------------------------
__global__ void ln_kernel(const float* __restrict__ in, float* __restrict__ out,
                          const float* __restrict__ g, const float* __restrict__ beta)
{
    int warp = threadIdx.x >> 5, lane = threadIdx.x & 31;
    int p = blockIdx.x * 8 + warp;
    float4 v = ((const float4*)(in + (size_t)p * Cc))[lane];
    float s = v.x + v.y + v.z + v.w;
    #pragma unroll
    for (int o = 16; o; o >>= 1) s += __shfl_xor_sync(0xffffffffu, s, o);
    float mean = s * (1.0f / Cc);
    float dx = v.x - mean, dy = v.y - mean, dz = v.z - mean, dw = v.w - mean;
    float q = dx*dx + dy*dy + dz*dz + dw*dw;
    #pragma unroll
    for (int o = 16; o; o >>= 1) q += __shfl_xor_sync(0xffffffffu, q, o);
    float rstd = rsqrtf(q * (1.0f / Cc) + 1e-5f);
    float4 gv = ((const float4*)g)[lane];
    float4 bv = ((const float4*)beta)[lane];
    float4 r;
    r.x = dx * rstd * gv.x + bv.x;
    r.y = dy * rstd * gv.y + bv.y;
    r.z = dz * rstd * gv.z + bv.z;
    r.w = dw * rstd * gv.w + bv.w;
    ((float4*)(out + (size_t)p * Cc))[lane] = r;
}

// ---------------------------------------------------------------------------
// Dynamic conv: logits = x @ conv_w + conv_b (20 per token), softmax over K
// per head, then causal depthwise window sum. Warp per token.
// ---------------------------------------------------------------------------
__global__ void conv_kernel(const float* __restrict__ XLN,
                            const float* __restrict__ cw,   // [C][H*K] for layer l
                            const float* __restrict__ cb,   // [H*K]
                            float* __restrict__ Y)
{
    int warp = threadIdx.x >> 5, lane = threadIdx.x & 31;
    int p = blockIdx.x * 8 + warp;
    int t = p / Bb, b = p - t * Bb;

    float4 xv = ((const float4*)(XLN + (size_t)p * Cc))[lane];
    int c0 = lane * 4;

    float part[HK];
    #pragma unroll
    for (int j = 0; j < HK; j++) part[j] = 0.0f;
    #pragma unroll
    for (int u = 0; u < 4; u++) {
        float xu = (&xv.x)[u];
        const float* wr = cw + (size_t)(c0 + u) * HK;
        #pragma unroll
        for (int j = 0; j < HK; j++) part[j] += xu * __ldg(wr + j);
    }
    // warp all-reduce 20 logits
    #pragma unroll
    for (int o = 16; o; o >>= 1) {
        #pragma unroll
        for (int j = 0; j < HK; j++)
            part[j] += __shfl_xor_sync(0xffffffffu, part[j], o);
    }

    int h = c0 >> 5;  // head of all 4 channels this lane owns (R=32)
    float lg[Kk];
    float mx = -1e30f;
    #pragma unroll
    for (int k = 0; k < Kk; k++) {
        lg[k] = part[h * Kk + k] + __ldg(cb + h * Kk + k);
        mx = fmaxf(mx, lg[k]);
    }
    float den = 0.0f;
    #pragma unroll
    for (int k = 0; k < Kk; k++) { lg[k] = expf(lg[k] - mx); den += lg[k]; }
    float inv = 1.0f / den;

    float4 acc = make_float4(0.f, 0.f, 0.f, 0.f);
    #pragma unroll
    for (int k = 0; k < Kk; k++) {
        int ts = t - (Kk - 1) + k;
        if (ts >= 0) {  // uniform branch across the warp
            float4 wv = ((const float4*)(XLN + ((size_t)ts * Bb + b) * Cc))[lane];
            float wk = lg[k] * inv;
            acc.x += wk * wv.x; acc.y += wk * wv.y;
            acc.z += wk * wv.z; acc.w += wk * wv.w;
        }
    }
    ((float4*)(Y + (size_t)p * Cc))[lane] = acc;
}

// ---------------------------------------------------------------------------
// Tiled fp32 GEMM: Cout[M][N] = op(A[M][Kd] @ W[Kd][N] + bias) (+res)
// 64x64 tile, BK=16, 256 threads, 4x4 microtile
// ---------------------------------------------------------------------------
template<bool RELU, bool RES>
__global__ void gemm_kernel(const float* __restrict__ A, const float* __restrict__ W,
                            const float* __restrict__ bias, const float* __restrict__ res,
                            float* __restrict__ Cout, int M, int N, int Kd)
{
    __shared__ float Ash[16][68];  // [k][m], pad 4 keeps float4 alignment
    __shared__ float Bsh[16][68];  // [k][n]

    const int bm = blockIdx.y * 64;
    const int bn = blockIdx.x * 64;
    const int tid = threadIdx.x;
    const int m0 = (tid >> 4) * 4;
    const int n0 = (tid & 15) * 4;

    // A-load mapping: row lr (0..63), k-quad lk
    const int lr = tid >> 2;
    const int lk = (tid & 3) * 4;
    // B-load mapping: k-row bk (0..15), n-quad bn4
    const int bk = tid >> 4;
    const int bn4 = (tid & 15) * 4;

    float acc[4][4] = {};

    for (int k0 = 0; k0 < Kd; k0 += 16) {
        float4 av = *(const float4*)(A + (size_t)(bm + lr) * Kd + k0 + lk);
        Ash[lk + 0][lr] = av.x; Ash[lk + 1][lr] = av.y;
        Ash[lk + 2][lr] = av.z; Ash[lk + 3][lr] = av.w;
        *(float4*)&Bsh[bk][bn4] =
            *(const float4*)(W + (size_t)(k0 + bk) * N + bn + bn4);
        __syncthreads();
        #pragma unroll
        for (int k = 0; k < 16; k++) {
            float4 a = *(const float4*)&Ash[k][m0];
            float4 bq = *(const float4*)&Bsh[k][n0];
            acc[0][0] += a.x * bq.x; acc[0][1] += a.x * bq.y;
            acc[0][2] += a.x * bq.z; acc[0][3] += a.x * bq.w;
            acc[1][0] += a.y * bq.x; acc[1][1] += a.y * bq.y;
            acc[1][2] += a.y * bq.z; acc[1][3] += a.y * bq.w;
            acc[2][0] += a.z * bq.x; acc[2][1] += a.z * bq.y;
            acc[2][2] += a.z * bq.z; acc[2][3] += a.z * bq.w;
            acc[3][0] += a.w * bq.x; acc[3][1] += a.w * bq.y;
            acc[3][2] += a.w * bq.z; acc[3][3] += a.w * bq.w;
        }
        __syncthreads();
    }

    #pragma unroll
    for (int i = 0; i < 4; i++) {
        int m = bm + m0 + i;
        float4 o;
        float* op = &o.x;
        #pragma unroll
        for (int j = 0; j < 4; j++) {
            float v = acc[i][j] + __ldg(bias + bn + n0 + j);
            if (RELU) v = fmaxf(v, 0.0f);
            op[j] = v;
        }
        if (RES) {
            float4 rv = *(const float4*)(res + (size_t)m * N + bn + n0);
            o.x += rv.x; o.y += rv.y; o.z += rv.z; o.w += rv.w;
        }
        *(float4*)(Cout + (size_t)m * N + bn + n0) = o;
    }
}

// ---------------------------------------------------------------------------
// Loss: pos/neg dots + logistic loss, block partial sums (deterministic)
// ---------------------------------------------------------------------------
__global__ void loss_kernel(const float* __restrict__ se,   // seq_emb in [t*B+b] layout
                            const float* __restrict__ emb,
                            const int* __restrict__ pos,
                            const int* __restrict__ neg,
                            float* __restrict__ pL, float* __restrict__ pM)
{
    int warp = threadIdx.x >> 5, lane = threadIdx.x & 31;
    int i = blockIdx.x * 8 + warp;          // row index in (B*T) order
    int b = i / Tt, t = i - b * Tt;
    int p = t * Bb + b;                     // our storage order

    float4 e  = ((const float4*)(se  + (size_t)p   * Cc))[lane];
    int pid = pos[i];
    int nid = neg[i];
    float4 pv = ((const float4*)(emb + (size_t)pid * Cc))[lane];
    float4 nv = ((const float4*)(emb + (size_t)nid * Cc))[lane];
    float dp = e.x*pv.x + e.y*pv.y + e.z*pv.z + e.w*pv.w;
    float dn = e.x*nv.x + e.y*nv.y + e.z*nv.z + e.w*nv.w;
    #pragma unroll
    for (int o = 16; o; o >>= 1) {
        dp += __shfl_xor_sync(0xffffffffu, dp, o);
        dn += __shfl_xor_sync(0xffffffffu, dn, o);
    }

    __shared__ float sL[8], sM[8];
    if (lane == 0) {
        float sp = 1.0f / (1.0f + expf(-dp));
        float sn = 1.0f / (1.0f + expf(-dn));
        float val = -logf(sp + 1e-24f) - logf(1.0f - sn + 1e-24f);
        float m = (pid != 0) ? 1.0f : 0.0f;
        sL[warp] = val * m;
        sM[warp] = m;
    }
    __syncthreads();
    if (threadIdx.x == 0) {
        float a = 0.f, mm = 0.f;
        #pragma unroll
        for (int w = 0; w < 8; w++) { a += sL[w]; mm += sM[w]; }
        pL[blockIdx.x] = a;
        pM[blockIdx.x] = mm;
    }
}

__global__ void reduce_kernel(const float* __restrict__ pL,
                              const float* __restrict__ pM,
                              float* __restrict__ out)
{
    __shared__ double sL[256], sM[256];
    double a = 0.0, m = 0.0;
    for (int i = threadIdx.x; i < NPART; i += 256) { a += pL[i]; m += pM[i]; }
    sL[threadIdx.x] = a; sM[threadIdx.x] = m;
    __syncthreads();
    for (int s = 128; s; s >>= 1) {
        if (threadIdx.x < s) {
            sL[threadIdx.x] += sL[threadIdx.x + s];
            sM[threadIdx.x] += sM[threadIdx.x + s];
        }
        __syncthreads();
    }
    if (threadIdx.x == 0) out[0] = (float)(sL[0] / sM[0]);
}

// ---------------------------------------------------------------------------
extern "C" void kernel_launch(void* const* d_in, const int* in_sizes, int n_in,
                              void* d_out, int out_size)
{
    const float* item_emb = (const float*)d_in[0];
    const float* conv_w   = (const float*)d_in[1];
    const float* conv_b   = (const float*)d_in[2];
    const float* ln_g     = (const float*)d_in[3];
    const float* ln_b     = (const float*)d_in[4];
    const float* fc1_w    = (const float*)d_in[5];
    const float* fc1_b    = (const float*)d_in[6];
    const float* fc2_w    = (const float*)d_in[7];
    const float* fc2_b    = (const float*)d_in[8];
    const float* sln_g    = (const float*)d_in[9];
    const float* sln_b    = (const float*)d_in[10];
    const int*   seq      = (const int*)d_in[11];
    const int*   pos      = (const int*)d_in[12];
    const int*   neg      = (const int*)d_in[13];

    float *X, *XLN, *Y, *Hb, *pL, *pM;
    cudaGetSymbolAddress((void**)&X,   g_X);
    cudaGetSymbolAddress((void**)&XLN, g_XLN);
    cudaGetSymbolAddress((void**)&Y,   g_Y);
    cudaGetSymbolAddress((void**)&Hb,  g_H);
    cudaGetSymbolAddress((void**)&pL,  g_pL);
    cudaGetSymbolAddress((void**)&pM,  g_pM);

    const int gr8 = BTt / 8;   // 12800 blocks, 8 warp-tokens each
    dim3 blk(256);

    embed_kernel<<<gr8, blk>>>(item_emb, seq, X);

    for (int l = 0; l < Ll; l++) {
        ln_kernel<<<gr8, blk>>>(X, XLN, sln_g, sln_b);
        conv_kernel<<<gr8, blk>>>(XLN, conv_w + (size_t)l * Cc * HK,
                                  conv_b + (size_t)l * HK, Y);
        ln_kernel<<<gr8, blk>>>(Y, XLN, ln_g + (size_t)l * Cc, ln_b + (size_t)l * Cc);
        // fc1: [BT,128] @ [128,512] -> H (relu)
        gemm_kernel<true, false><<<dim3(Ff / 64, BTt / 64), 256>>>(
            XLN, fc1_w + (size_t)l * Cc * Ff, fc1_b + (size_t)l * Ff,
            nullptr, Hb, BTt, Ff, Cc);
        // fc2: [BT,512] @ [512,128] + bias + residual(XLN) -> X
        gemm_kernel<false, true><<<dim3(Cc / 64, BTt / 64), 256>>>(
            Hb, fc2_w + (size_t)l * Ff * Cc, fc2_b + (size_t)l * Cc,
            XLN, X, BTt, Cc, Ff);
    }

    ln_kernel<<<gr8, blk>>>(X, XLN, sln_g, sln_b);
    loss_kernel<<<gr8, blk>>>(XLN, item_emb, pos, neg, pL, pM);
    reduce_kernel<<<1, 256>>>(pL, pM, (float*)d_out);
}

// round 2
// speedup vs baseline: 1.4780x; 1.4780x over previous
#include <cuda_runtime.h>
#include <math.h>
#include <stdint.h>

// Problem constants
#define Tt 200
#define Bb 512
#define Cc 128
#define Hh 4
#define Kk 5
#define Ff 512
#define Ll 2
#define BTt (Tt*Bb)        // 102400 tokens
#define HK  (Hh*Kk)        // 20
#define NPART (BTt/8)      // 12800 partial sums

// Scratch
__device__ float g_X  [BTt*Cc];
__device__ float g_XLN[BTt*Cc];
__device__ float g_Y  [BTt*Cc];
__device__ float g_H  [BTt*Ff];
__device__ float g_pL [NPART];
__device__ float g_pM [NPART];

// ---------------------------------------------------------------------------
__global__ void embed_kernel(const float* __restrict__ emb,
                             const int* __restrict__ seq,
                             float* __restrict__ X)
{
    int warp = threadIdx.x >> 5, lane = threadIdx.x & 31;
    int p = blockIdx.x * 8 + warp;
    int t = p / Bb, b = p - t * Bb;
    int id = seq[b * Tt + t];
    float4 v = ((const float4*)(emb + (size_t)id * Cc))[lane];
    ((float4*)(X + (size_t)p * Cc))[lane] = v;
}

// ---------------------------------------------------------------------------
__global__ void ln_kernel(const float* __restrict__ in, float* __restrict__ out,
                          const float* __restrict__ g, const float* __restrict__ beta)
{
    int warp = threadIdx.x >> 5, lane = threadIdx.x & 31;
    int p = blockIdx.x * 8 + warp;
    float4 v = ((const float4*)(in + (size_t)p * Cc))[lane];
    float s = v.x + v.y + v.z + v.w;
    #pragma unroll
    for (int o = 16; o; o >>= 1) s += __shfl_xor_sync(0xffffffffu, s, o);
    float mean = s * (1.0f / Cc);
    float dx = v.x - mean, dy = v.y - mean, dz = v.z - mean, dw = v.w - mean;
    float q = dx*dx + dy*dy + dz*dz + dw*dw;
    #pragma unroll
    for (int o = 16; o; o >>= 1) q += __shfl_xor_sync(0xffffffffu, q, o);
    float rstd = rsqrtf(q * (1.0f / Cc) + 1e-5f);
    float4 gv = ((const float4*)g)[lane];
    float4 bv = ((const float4*)beta)[lane];
    float4 r;
    r.x = dx * rstd * gv.x + bv.x;
    r.y = dy * rstd * gv.y + bv.y;
    r.z = dz * rstd * gv.z + bv.z;
    r.w = dw * rstd * gv.w + bv.w;
    ((float4*)(out + (size_t)p * Cc))[lane] = r;
}

// ---------------------------------------------------------------------------
__global__ void conv_kernel(const float* __restrict__ XLN,
                            const float* __restrict__ cw,
                            const float* __restrict__ cb,
                            float* __restrict__ Y)
{
    int warp = threadIdx.x >> 5, lane = threadIdx.x & 31;
    int p = blockIdx.x * 8 + warp;
    int t = p / Bb, b = p - t * Bb;

    float4 xv = ((const float4*)(XLN + (size_t)p * Cc))[lane];
    int c0 = lane * 4;

    float part[HK];
    #pragma unroll
    for (int j = 0; j < HK; j++) part[j] = 0.0f;
    #pragma unroll
    for (int u = 0; u < 4; u++) {
        float xu = (&xv.x)[u];
        const float* wr = cw + (size_t)(c0 + u) * HK;
        #pragma unroll
        for (int j = 0; j < HK; j++) part[j] += xu * __ldg(wr + j);
    }
    #pragma unroll
    for (int o = 16; o; o >>= 1) {
        #pragma unroll
        for (int j = 0; j < HK; j++)
            part[j] += __shfl_xor_sync(0xffffffffu, part[j], o);
    }

    int h = c0 >> 5;
    float lg[Kk];
    float mx = -1e30f;
    #pragma unroll
    for (int k = 0; k < Kk; k++) {
        lg[k] = part[h * Kk + k] + __ldg(cb + h * Kk + k);
        mx = fmaxf(mx, lg[k]);
    }
    float den = 0.0f;
    #pragma unroll
    for (int k = 0; k < Kk; k++) { lg[k] = expf(lg[k] - mx); den += lg[k]; }
    float inv = 1.0f / den;

    float4 acc = make_float4(0.f, 0.f, 0.f, 0.f);
    #pragma unroll
    for (int k = 0; k < Kk; k++) {
        int ts = t - (Kk - 1) + k;
        if (ts >= 0) {
            float4 wv = ((const float4*)(XLN + ((size_t)ts * Bb + b) * Cc))[lane];
            float wk = lg[k] * inv;
            acc.x += wk * wv.x; acc.y += wk * wv.y;
            acc.z += wk * wv.z; acc.w += wk * wv.w;
        }
    }
    ((float4*)(Y + (size_t)p * Cc))[lane] = acc;
}

// ---------------------------------------------------------------------------
// TF32 tensor-core GEMM: 128x64x32 block tile, 8 warps, m16n8k8 mma
// ---------------------------------------------------------------------------
__device__ __forceinline__ uint32_t f2tf32(float f) {
    uint32_t u;
    asm("cvt.rna.tf32.f32 %0, %1;" : "=r"(u) : "f"(f));
    return u;
}

__device__ __forceinline__ void mma_tf32(float* c, const uint32_t* a, const uint32_t* b) {
    asm volatile(
        "mma.sync.aligned.m16n8k8.row.col.f32.tf32.tf32.f32 "
        "{%0,%1,%2,%3}, {%4,%5,%6,%7}, {%8,%9}, {%0,%1,%2,%3};\n"
        : "+f"(c[0]), "+f"(c[1]), "+f"(c[2]), "+f"(c[3])
        : "r"(a[0]), "r"(a[1]), "r"(a[2]), "r"(a[3]), "r"(b[0]), "r"(b[1]));
}

#define AS_STRIDE 40   // 32 + 8: fragment LDS bank = (8*row + k) % 32, conflict-free
#define BS_STRIDE 72   // 64 + 8: fragment LDS bank = (8*k + n) % 32, conflict-free

template<bool RELU, bool RES>
__global__ __launch_bounds__(256, 2)
void gemm_tc(const float* __restrict__ A, const float* __restrict__ W,
             const float* __restrict__ bias, const float* __restrict__ res,
             float* __restrict__ Cout, int M, int N, int Kd)
{
    __shared__ uint32_t As[128 * AS_STRIDE];  // [m][k]
    __shared__ uint32_t Bs[32 * BS_STRIDE];   // [k][n]

    const int bm = blockIdx.y * 128;
    const int bn = blockIdx.x * 64;
    const int t = threadIdx.x;
    const int warp = t >> 5, lane = t & 31;
    const int wm = warp & 3, wn = warp >> 2;
    const int g = lane >> 2, i = lane & 3;

    const int lrow = t >> 3;          // 0..31
    const int lcol = (t & 7) * 4;     // 0..28

    float4 pa[4], pb[2];
    {
        const float* Ab = A + (size_t)(bm + lrow) * Kd + lcol;
        #pragma unroll
        for (int p = 0; p < 4; p++)
            pa[p] = *(const float4*)(Ab + (size_t)(p * 32) * Kd);
        const float* Wb = W + (size_t)lrow * N + bn + lcol;
        #pragma unroll
        for (int p = 0; p < 2; p++)
            pb[p] = *(const float4*)(Wb + p * 32);
    }

    float acc[2][4][4];
    #pragma unroll
    for (int mi = 0; mi < 2; mi++)
        #pragma unroll
        for (int ni = 0; ni < 4; ni++)
            #pragma unroll
            for (int q = 0; q < 4; q++) acc[mi][ni][q] = 0.0f;

    const int nIter = Kd >> 5;
    for (int it = 0; it < nIter; ++it) {
        // regs -> smem (convert to tf32 once here)
        #pragma unroll
        for (int p = 0; p < 4; p++) {
            uint32_t* s = &As[(p * 32 + lrow) * AS_STRIDE + lcol];
            s[0] = f2tf32(pa[p].x); s[1] = f2tf32(pa[p].y);
            s[2] = f2tf32(pa[p].z); s[3] = f2tf32(pa[p].w);
        }
        #pragma unroll
        for (int p = 0; p < 2; p++) {
            uint32_t* s = &Bs[lrow * BS_STRIDE + lcol + p * 32];
            s[0] = f2tf32(pb[p].x); s[1] = f2tf32(pb[p].y);
            s[2] = f2tf32(pb[p].z); s[3] = f2tf32(pb[p].w);
        }
        __syncthreads();

        // prefetch next K-slab while compute runs
        if (it + 1 < nIter) {
            const int k0 = (it + 1) << 5;
            const float* Ab = A + (size_t)(bm + lrow) * Kd + k0 + lcol;
            #pragma unroll
            for (int p = 0; p < 4; p++)
                pa[p] = *(const float4*)(Ab + (size_t)(p * 32) * Kd);
            const float* Wb = W + (size_t)(k0 + lrow) * N + bn + lcol;
            #pragma unroll
            for (int p = 0; p < 2; p++)
                pb[p] = *(const float4*)(Wb + p * 32);
        }

        #pragma unroll
        for (int kb = 0; kb < 32; kb += 8) {
            uint32_t af[2][4], bf[4][2];
            #pragma unroll
            for (int mi = 0; mi < 2; mi++) {
                int base = (wm * 32 + mi * 16 + g) * AS_STRIDE + kb + i;
                af[mi][0] = As[base];
                af[mi][1] = As[base + 8 * AS_STRIDE];
                af[mi][2] = As[base + 4];
                af[mi][3] = As[base + 8 * AS_STRIDE + 4];
            }
            #pragma unroll
            for (int ni = 0; ni < 4; ni++) {
                int base = (kb + i) * BS_STRIDE + wn * 32 + ni * 8 + g;
                bf[ni][0] = Bs[base];
                bf[ni][1] = Bs[base + 4 * BS_STRIDE];
            }
            #pragma unroll
            for (int mi = 0; mi < 2; mi++)
                #pragma unroll
                for (int ni = 0; ni < 4; ni++)
                    mma_tf32(acc[mi][ni], af[mi], bf[ni]);
        }
        __syncthreads();
    }

    // Epilogue
    #pragma unroll
    for (int mi = 0; mi < 2; mi++) {
        #pragma unroll
        for (int ni = 0; ni < 4; ni++) {
            int row = bm + wm * 32 + mi * 16 + g;
            int col = bn + wn * 32 + ni * 8 + 2 * i;
            float b0 = __ldg(bias + col), b1 = __ldg(bias + col + 1);
            float v0 = acc[mi][ni][0] + b0, v1 = acc[mi][ni][1] + b1;
            float v2 = acc[mi][ni][2] + b0, v3 = acc[mi][ni][3] + b1;
            if (RELU) {
                v0 = fmaxf(v0, 0.f); v1 = fmaxf(v1, 0.f);
                v2 = fmaxf(v2, 0.f); v3 = fmaxf(v3, 0.f);
            }
            if (RES) {
                float2 r0 = *(const float2*)(res + (size_t)row * N + col);
                float2 r1 = *(const float2*)(res + (size_t)(row + 8) * N + col);
                v0 += r0.x; v1 += r0.y; v2 += r1.x; v3 += r1.y;
            }
            float2 o0 = make_float2(v0, v1);
            float2 o1 = make_float2(v2, v3);
            *(float2*)(Cout + (size_t)row * N + col) = o0;
            *(float2*)(Cout + (size_t)(row + 8) * N + col) = o1;
        }
    }
}

// ---------------------------------------------------------------------------
__global__ void loss_kernel(const float* __restrict__ se,
                            const float* __restrict__ emb,
                            const int* __restrict__ pos,
                            const int* __restrict__ neg,
                            float* __restrict__ pL, float* __restrict__ pM)
{
    int warp = threadIdx.x >> 5, lane = threadIdx.x & 31;
    int i = blockIdx.x * 8 + warp;
    int b = i / Tt, t = i - b * Tt;
    int p = t * Bb + b;

    float4 e  = ((const float4*)(se  + (size_t)p   * Cc))[lane];
    int pid = pos[i];
    int nid = neg[i];
    float4 pv = ((const float4*)(emb + (size_t)pid * Cc))[lane];
    float4 nv = ((const float4*)(emb + (size_t)nid * Cc))[lane];
    float dp = e.x*pv.x + e.y*pv.y + e.z*pv.z + e.w*pv.w;
    float dn = e.x*nv.x + e.y*nv.y + e.z*nv.z + e.w*nv.w;
    #pragma unroll
    for (int o = 16; o; o >>= 1) {
        dp += __shfl_xor_sync(0xffffffffu, dp, o);
        dn += __shfl_xor_sync(0xffffffffu, dn, o);
    }

    __shared__ float sL[8], sM[8];
    if (lane == 0) {
        float sp = 1.0f / (1.0f + expf(-dp));
        float sn = 1.0f / (1.0f + expf(-dn));
        float val = -logf(sp + 1e-24f) - logf(1.0f - sn + 1e-24f);
        float m = (pid != 0) ? 1.0f : 0.0f;
        sL[warp] = val * m;
        sM[warp] = m;
    }
    __syncthreads();
    if (threadIdx.x == 0) {
        float a = 0.f, mm = 0.f;
        #pragma unroll
        for (int w = 0; w < 8; w++) { a += sL[w]; mm += sM[w]; }
        pL[blockIdx.x] = a;
        pM[blockIdx.x] = mm;
    }
}

__global__ void reduce_kernel(const float* __restrict__ pL,
                              const float* __restrict__ pM,
                              float* __restrict__ out)
{
    __shared__ double sL[256], sM[256];
    double a = 0.0, m = 0.0;
    for (int i = threadIdx.x; i < NPART; i += 256) { a += pL[i]; m += pM[i]; }
    sL[threadIdx.x] = a; sM[threadIdx.x] = m;
    __syncthreads();
    for (int s = 128; s; s >>= 1) {
        if (threadIdx.x < s) {
            sL[threadIdx.x] += sL[threadIdx.x + s];
            sM[threadIdx.x] += sM[threadIdx.x + s];
        }
        __syncthreads();
    }
    if (threadIdx.x == 0) out[0] = (float)(sL[0] / sM[0]);
}

// ---------------------------------------------------------------------------
extern "C" void kernel_launch(void* const* d_in, const int* in_sizes, int n_in,
                              void* d_out, int out_size)
{
    const float* item_emb = (const float*)d_in[0];
    const float* conv_w   = (const float*)d_in[1];
    const float* conv_b   = (const float*)d_in[2];
    const float* ln_g     = (const float*)d_in[3];
    const float* ln_b     = (const float*)d_in[4];
    const float* fc1_w    = (const float*)d_in[5];
    const float* fc1_b    = (const float*)d_in[6];
    const float* fc2_w    = (const float*)d_in[7];
    const float* fc2_b    = (const float*)d_in[8];
    const float* sln_g    = (const float*)d_in[9];
    const float* sln_b    = (const float*)d_in[10];
    const int*   seq      = (const int*)d_in[11];
    const int*   pos      = (const int*)d_in[12];
    const int*   neg      = (const int*)d_in[13];

    float *X, *XLN, *Y, *Hb, *pL, *pM;
    cudaGetSymbolAddress((void**)&X,   g_X);
    cudaGetSymbolAddress((void**)&XLN, g_XLN);
    cudaGetSymbolAddress((void**)&Y,   g_Y);
    cudaGetSymbolAddress((void**)&Hb,  g_H);
    cudaGetSymbolAddress((void**)&pL,  g_pL);
    cudaGetSymbolAddress((void**)&pM,  g_pM);

    const int gr8 = BTt / 8;
    dim3 blk(256);

    embed_kernel<<<gr8, blk>>>(item_emb, seq, X);

    for (int l = 0; l < Ll; l++) {
        ln_kernel<<<gr8, blk>>>(X, XLN, sln_g, sln_b);
        conv_kernel<<<gr8, blk>>>(XLN, conv_w + (size_t)l * Cc * HK,
                                  conv_b + (size_t)l * HK, Y);
        ln_kernel<<<gr8, blk>>>(Y, XLN, ln_g + (size_t)l * Cc, ln_b + (size_t)l * Cc);
        gemm_tc<true, false><<<dim3(Ff / 64, BTt / 128), 256>>>(
            XLN, fc1_w + (size_t)l * Cc * Ff, fc1_b + (size_t)l * Ff,
            nullptr, Hb, BTt, Ff, Cc);
        gemm_tc<false, true><<<dim3(Cc / 64, BTt / 128), 256>>>(
            Hb, fc2_w + (size_t)l * Ff * Cc, fc2_b + (size_t)l * Cc,
            XLN, X, BTt, Cc, Ff);
    }

    ln_kernel<<<gr8, blk>>>(X, XLN, sln_g, sln_b);
    loss_kernel<<<gr8, blk>>>(XLN, item_emb, pos, neg, pL, pM);
    reduce_kernel<<<1, 256>>>(pL, pM, (float*)d_out);
}

// round 4
// speedup vs baseline: 1.8694x; 1.2648x over previous
#include <cuda_runtime.h>
#include <cuda_bf16.h>
#include <math.h>
#include <stdint.h>

// Problem constants
#define Tt 200
#define Bb 512
#define Cc 128
#define Hh 4
#define Kk 5
#define Ff 512
#define Ll 2
#define BTt (Tt*Bb)        // 102400 tokens
#define HK  (Hh*Kk)        // 20
#define NPART (BTt/8)

// Scratch
__device__ float g_X  [BTt*Cc];
__device__ float g_XLN[BTt*Cc];
__device__ float g_Y  [BTt*Cc];
__device__ __nv_bfloat16 g_XLNb[BTt*Cc];   // bf16 twin of post-conv LN (GEMM A)
__device__ __nv_bfloat16 g_Hb  [BTt*Ff];   // bf16 hidden
__device__ __nv_bfloat16 g_WT1 [Ll*Ff*Cc]; // fc1_w transposed [N=F][K=C] bf16
__device__ __nv_bfloat16 g_WT2 [Ll*Cc*Ff]; // fc2_w transposed [N=C][K=F] bf16
__device__ float g_pL [NPART];
__device__ float g_pM [NPART];

// ---------------------------------------------------------------------------
// helpers
// ---------------------------------------------------------------------------
__device__ __forceinline__ uint32_t smem_to_u32(const void* p) {
    uint32_t a;
    asm("{ .reg .u64 t; cvta.to.shared.u64 t, %1; cvt.u32.u64 %0, t; }" : "=r"(a) : "l"(p));
    return a;
}
__device__ __forceinline__ void mma_bf16(float* c, const uint32_t* a, const uint32_t* b) {
    asm volatile(
        "mma.sync.aligned.m16n8k16.row.col.f32.bf16.bf16.f32 "
        "{%0,%1,%2,%3}, {%4,%5,%6,%7}, {%8,%9}, {%0,%1,%2,%3};\n"
        : "+f"(c[0]), "+f"(c[1]), "+f"(c[2]), "+f"(c[3])
        : "r"(a[0]), "r"(a[1]), "r"(a[2]), "r"(a[3]), "r"(b[0]), "r"(b[1]));
}
__device__ __forceinline__ void ldsm4(uint32_t* r, uint32_t addr) {
    asm volatile("ldmatrix.sync.aligned.m8n8.x4.shared.b16 {%0,%1,%2,%3}, [%4];"
        : "=r"(r[0]), "=r"(r[1]), "=r"(r[2]), "=r"(r[3]) : "r"(addr));
}
__device__ __forceinline__ void cp16(uint32_t dst, const void* src) {
    asm volatile("cp.async.cg.shared.global [%0], [%1], 16;" :: "r"(dst), "l"(src));
}
#define CP_COMMIT() asm volatile("cp.async.commit_group;" ::: "memory")
#define CP_WAIT1()  asm volatile("cp.async.wait_group 1;" ::: "memory")
#define CP_WAIT0()  asm volatile("cp.async.wait_group 0;" ::: "memory")

// ---------------------------------------------------------------------------
__global__ void embed_kernel(const float* __restrict__ emb,
                             const int* __restrict__ seq,
                             float* __restrict__ X)
{
    int warp = threadIdx.x >> 5, lane = threadIdx.x & 31;
    int p = blockIdx.x * 8 + warp;
    int t = p / Bb, b = p - t * Bb;
    int id = seq[b * Tt + t];
    float4 v = ((const float4*)(emb + (size_t)id * Cc))[lane];
    ((float4*)(X + (size_t)p * Cc))[lane] = v;
}

// ---------------------------------------------------------------------------
__global__ void ln_kernel(const float* __restrict__ in, float* __restrict__ out,
                          __nv_bfloat16* __restrict__ outb,
                          const float* __restrict__ g, const float* __restrict__ beta)
{
    int warp = threadIdx.x >> 5, lane = threadIdx.x & 31;
    int p = blockIdx.x * 8 + warp;
    float4 v = ((const float4*)(in + (size_t)p * Cc))[lane];
    float s = v.x + v.y + v.z + v.w;
    #pragma unroll
    for (int o = 16; o; o >>= 1) s += __shfl_xor_sync(0xffffffffu, s, o);
    float mean = s * (1.0f / Cc);
    float dx = v.x - mean, dy = v.y - mean, dz = v.z - mean, dw = v.w - mean;
    float q = dx*dx + dy*dy + dz*dz + dw*dw;
    #pragma unroll
    for (int o = 16; o; o >>= 1) q += __shfl_xor_sync(0xffffffffu, q, o);
    float rstd = rsqrtf(q * (1.0f / Cc) + 1e-5f);
    float4 gv = ((const float4*)g)[lane];
    float4 bv = ((const float4*)beta)[lane];
    float4 r;
    r.x = dx * rstd * gv.x + bv.x;
    r.y = dy * rstd * gv.y + bv.y;
    r.z = dz * rstd * gv.z + bv.z;
    r.w = dw * rstd * gv.w + bv.w;
    ((float4*)(out + (size_t)p * Cc))[lane] = r;
    if (outb) {
        __nv_bfloat162 h0 = __floats2bfloat162_rn(r.x, r.y);
        __nv_bfloat162 h1 = __floats2bfloat162_rn(r.z, r.w);
        uint2 u;
        u.x = *(uint32_t*)&h0; u.y = *(uint32_t*)&h1;
        *(uint2*)(outb + (size_t)p * Cc + lane * 4) = u;
    }
}

// ---------------------------------------------------------------------------
__global__ void conv_kernel(const float* __restrict__ XLN,
                            const float* __restrict__ cw,
                            const float* __restrict__ cb,
                            float* __restrict__ Y)
{
    int warp = threadIdx.x >> 5, lane = threadIdx.x & 31;
    int p = blockIdx.x * 8 + warp;
    int t = p / Bb, b = p - t * Bb;

    float4 xv = ((const float4*)(XLN + (size_t)p * Cc))[lane];
    int c0 = lane * 4;

    float part[HK];
    #pragma unroll
    for (int j = 0; j < HK; j++) part[j] = 0.0f;
    #pragma unroll
    for (int u = 0; u < 4; u++) {
        float xu = (&xv.x)[u];
        const float* wr = cw + (size_t)(c0 + u) * HK;
        #pragma unroll
        for (int j = 0; j < HK; j++) part[j] += xu * __ldg(wr + j);
    }
    #pragma unroll
    for (int o = 16; o; o >>= 1) {
        #pragma unroll
        for (int j = 0; j < HK; j++)
            part[j] += __shfl_xor_sync(0xffffffffu, part[j], o);
    }

    int h = c0 >> 5;
    float lg[Kk];
    float mx = -1e30f;
    #pragma unroll
    for (int k = 0; k < Kk; k++) {
        lg[k] = part[h * Kk + k] + __ldg(cb + h * Kk + k);
        mx = fmaxf(mx, lg[k]);
    }
    float den = 0.0f;
    #pragma unroll
    for (int k = 0; k < Kk; k++) { lg[k] = expf(lg[k] - mx); den += lg[k]; }
    float inv = 1.0f / den;

    float4 acc = make_float4(0.f, 0.f, 0.f, 0.f);
    #pragma unroll
    for (int k = 0; k < Kk; k++) {
        int ts = t - (Kk - 1) + k;
        if (ts >= 0) {
            float4 wv = ((const float4*)(XLN + ((size_t)ts * Bb + b) * Cc))[lane];
            float wk = lg[k] * inv;
            acc.x += wk * wv.x; acc.y += wk * wv.y;
            acc.z += wk * wv.z; acc.w += wk * wv.w;
        }
    }
    ((float4*)(Y + (size_t)p * Cc))[lane] = acc;
}

// ---------------------------------------------------------------------------
// Weight transpose+convert: in [Kd, Nn] fp32 -> out [Nn, Kd] bf16
// ---------------------------------------------------------------------------
__global__ void wt_kernel(const float* __restrict__ in, __nv_bfloat16* __restrict__ out,
                          int Kd, int Nn)
{
    int idx = blockIdx.x * 256 + threadIdx.x;
    int n = idx / Kd, k = idx - n * Kd;
    out[idx] = __float2bfloat16_rn(in[(size_t)k * Nn + n]);
}

// ---------------------------------------------------------------------------
// bf16 mma.sync GEMM: block 128(M) x 128(N) x 32(K), 256 threads, 8 warps 4x2.
// A [M][KD] bf16 K-major, Wt [N][KD] bf16 K-major.
// Smem layout per tile: [row][64B] with 16B-chunk XOR swizzle:
//   off(row, kb16) = row*64 + ((kb16 ^ ((row>>1)&3)) << 4)
// conflict-free for cp.async STS.128 and all ldmatrix phases.
// FC1: +bias, relu, bf16 out (stride Ff). FC2: +bias +res, fp32 out (stride Cc).
// ---------------------------------------------------------------------------
template<int KD, bool FC1>
__global__ void __launch_bounds__(256, 2)
gemm_bf16(const __nv_bfloat16* __restrict__ A,
          const __nv_bfloat16* __restrict__ Wt,
          const float* __restrict__ bias,
          const float* __restrict__ res,
          void* __restrict__ outp)
{
    __shared__ __align__(1024) char sm[2 * 16384];  // [buf][A 8KB | B 8KB]

    const int tid = threadIdx.x;
    const int wid = tid >> 5, lane = tid & 31;
    const int wm = wid & 3, wn = wid >> 2;         // 4 x 2 warp grid
    const int bm = blockIdx.y * 128, bn = blockIdx.x * 128;

    const uint32_t sA = smem_to_u32(sm);

    // ---- load mapping: thread t handles chunks (row=t>>2, kb=t&3) and (+64 rows)
    const int arow = tid >> 2, akb = tid & 3;
    const uint32_t loff = arow * 64 + ((akb ^ ((arow >> 1) & 3)) << 4);
    const __nv_bfloat16* pa = A  + (size_t)(bm + arow) * KD + akb * 8;
    const __nv_bfloat16* pb = Wt + (size_t)(bn + arow) * KD + akb * 8;

    // ---- ldmatrix per-lane address components
    const int lgrp = lane >> 3, l7 = lane & 7;
    uint32_t aoff[2]; int axor[2];
    #pragma unroll
    for (int mi = 0; mi < 2; mi++) {
        int r = wm * 32 + mi * 16 + l7 + ((lgrp & 1) << 3);
        aoff[mi] = r * 64; axor[mi] = (r >> 1) & 3;
    }
    const int cA = lgrp >> 1;
    uint32_t boff[4]; int bxor[4];
    #pragma unroll
    for (int nt = 0; nt < 4; nt++) {
        int r = wn * 64 + nt * 16 + l7 + ((lgrp >> 1) << 3);
        boff[nt] = r * 64; bxor[nt] = (r >> 1) & 3;
    }
    const int cB = lgrp & 1;

    float acc[2][8][4];
    #pragma unroll
    for (int mi = 0; mi < 2; mi++)
        #pragma unroll
        for (int ni = 0; ni < 8; ni++)
            #pragma unroll
            for (int q = 0; q < 4; q++) acc[mi][ni][q] = 0.0f;

    const int NIT = KD / 32;

    // prologue load
    {
        uint32_t dA = sA + loff;
        cp16(dA,        pa);
        cp16(dA + 4096, pa + (size_t)64 * KD);
        cp16(dA + 8192, pb);
        cp16(dA + 12288, pb + (size_t)64 * KD);
        CP_COMMIT();
    }

    for (int it = 0; it < NIT; it++) {
        if (it + 1 < NIT) {
            uint32_t dA = sA + ((it + 1) & 1) * 16384 + loff;
            const __nv_bfloat16* qa = pa + (it + 1) * 32;
            const __nv_bfloat16* qb = pb + (it + 1) * 32;
            cp16(dA,        qa);
            cp16(dA + 4096, qa + (size_t)64 * KD);
            cp16(dA + 8192, qb);
            cp16(dA + 12288, qb + (size_t)64 * KD);
            CP_COMMIT();
            CP_WAIT1();
        } else {
            CP_WAIT0();
        }
        __syncthreads();

        const uint32_t bufA = sA + (it & 1) * 16384;
        const uint32_t bufB = bufA + 8192;

        #pragma unroll
        for (int s = 0; s < 2; s++) {
            uint32_t af[2][4], bf[4][4];
            #pragma unroll
            for (int mi = 0; mi < 2; mi++)
                ldsm4(af[mi], bufA + aoff[mi] + (((2 * s + cA) ^ axor[mi]) << 4));
            #pragma unroll
            for (int nt = 0; nt < 4; nt++)
                ldsm4(bf[nt], bufB + boff[nt] + (((2 * s + cB) ^ bxor[nt]) << 4));
            #pragma unroll
            for (int mi = 0; mi < 2; mi++)
                #pragma unroll
                for (int ni = 0; ni < 8; ni++)
                    mma_bf16(acc[mi][ni], af[mi], &bf[ni >> 1][(ni & 1) * 2]);
        }
        __syncthreads();
    }

    // ---- epilogue
    const int g = lane >> 2, i4 = lane & 3;
    #pragma unroll
    for (int mi = 0; mi < 2; mi++) {
        int r0 = bm + wm * 32 + mi * 16 + g;
        #pragma unroll
        for (int ni = 0; ni < 8; ni++) {
            int col = bn + wn * 64 + ni * 8 + i4 * 2;
            float b0 = __ldg(bias + col), b1 = __ldg(bias + col + 1);
            float v0 = acc[mi][ni][0] + b0, v1 = acc[mi][ni][1] + b1;
            float v2 = acc[mi][ni][2] + b0, v3 = acc[mi][ni][3] + b1;
            if (FC1) {
                v0 = fmaxf(v0, 0.f); v1 = fmaxf(v1, 0.f);
                v2 = fmaxf(v2, 0.f); v3 = fmaxf(v3, 0.f);
                __nv_bfloat16* O = (__nv_bfloat16*)outp;
                *(__nv_bfloat162*)(O + (size_t)r0 * Ff + col) =
                    __floats2bfloat162_rn(v0, v1);
                *(__nv_bfloat162*)(O + (size_t)(r0 + 8) * Ff + col) =
                    __floats2bfloat162_rn(v2, v3);
            } else {
                float* O = (float*)outp;
                float2 rv0 = *(const float2*)(res + (size_t)r0 * Cc + col);
                float2 rv1 = *(const float2*)(res + (size_t)(r0 + 8) * Cc + col);
                *(float2*)(O + (size_t)r0 * Cc + col) =
                    make_float2(v0 + rv0.x, v1 + rv0.y);
                *(float2*)(O + (size_t)(r0 + 8) * Cc + col) =
                    make_float2(v2 + rv1.x, v3 + rv1.y);
            }
        }
    }
}

// ---------------------------------------------------------------------------
__global__ void loss_kernel(const float* __restrict__ se,
                            const float* __restrict__ emb,
                            const int* __restrict__ pos,
                            const int* __restrict__ neg,
                            float* __restrict__ pL, float* __restrict__ pM)
{
    int warp = threadIdx.x >> 5, lane = threadIdx.x & 31;
    int i = blockIdx.x * 8 + warp;
    int b = i / Tt, t = i - b * Tt;
    int p = t * Bb + b;

    float4 e  = ((const float4*)(se  + (size_t)p   * Cc))[lane];
    int pid = pos[i];
    int nid = neg[i];
    float4 pv = ((const float4*)(emb + (size_t)pid * Cc))[lane];
    float4 nv = ((const float4*)(emb + (size_t)nid * Cc))[lane];
    float dp = e.x*pv.x + e.y*pv.y + e.z*pv.z + e.w*pv.w;
    float dn = e.x*nv.x + e.y*nv.y + e.z*nv.z + e.w*nv.w;
    #pragma unroll
    for (int o = 16; o; o >>= 1) {
        dp += __shfl_xor_sync(0xffffffffu, dp, o);
        dn += __shfl_xor_sync(0xffffffffu, dn, o);
    }

    __shared__ float sL[8], sM[8];
    if (lane == 0) {
        float sp = 1.0f / (1.0f + expf(-dp));
        float sn = 1.0f / (1.0f + expf(-dn));
        float val = -logf(sp + 1e-24f) - logf(1.0f - sn + 1e-24f);
        float m = (pid != 0) ? 1.0f : 0.0f;
        sL[warp] = val * m;
        sM[warp] = m;
    }
    __syncthreads();
    if (threadIdx.x == 0) {
        float a = 0.f, mm = 0.f;
        #pragma unroll
        for (int w = 0; w < 8; w++) { a += sL[w]; mm += sM[w]; }
        pL[blockIdx.x] = a;
        pM[blockIdx.x] = mm;
    }
}

__global__ void reduce_kernel(const float* __restrict__ pL,
                              const float* __restrict__ pM,
                              float* __restrict__ out)
{
    __shared__ double sL[256], sM[256];
    double a = 0.0, m = 0.0;
    for (int i = threadIdx.x; i < NPART; i += 256) { a += pL[i]; m += pM[i]; }
    sL[threadIdx.x] = a; sM[threadIdx.x] = m;
    __syncthreads();
    for (int s = 128; s; s >>= 1) {
        if (threadIdx.x < s) {
            sL[threadIdx.x] += sL[threadIdx.x + s];
            sM[threadIdx.x] += sM[threadIdx.x + s];
        }
        __syncthreads();
    }
    if (threadIdx.x == 0) out[0] = (float)(sL[0] / sM[0]);
}

// ---------------------------------------------------------------------------
extern "C" void kernel_launch(void* const* d_in, const int* in_sizes, int n_in,
                              void* d_out, int out_size)
{
    const float* item_emb = (const float*)d_in[0];
    const float* conv_w   = (const float*)d_in[1];
    const float* conv_b   = (const float*)d_in[2];
    const float* ln_g     = (const float*)d_in[3];
    const float* ln_b     = (const float*)d_in[4];
    const float* fc1_w    = (const float*)d_in[5];
    const float* fc1_b    = (const float*)d_in[6];
    const float* fc2_w    = (const float*)d_in[7];
    const float* fc2_b    = (const float*)d_in[8];
    const float* sln_g    = (const float*)d_in[9];
    const float* sln_b    = (const float*)d_in[10];
    const int*   seq      = (const int*)d_in[11];
    const int*   pos      = (const int*)d_in[12];
    const int*   neg      = (const int*)d_in[13];

    float *X, *XLN, *Y, *pL, *pM;
    __nv_bfloat16 *XLNb, *Hb, *WT1, *WT2;
    cudaGetSymbolAddress((void**)&X,    g_X);
    cudaGetSymbolAddress((void**)&XLN,  g_XLN);
    cudaGetSymbolAddress((void**)&Y,    g_Y);
    cudaGetSymbolAddress((void**)&XLNb, g_XLNb);
    cudaGetSymbolAddress((void**)&Hb,   g_Hb);
    cudaGetSymbolAddress((void**)&WT1,  g_WT1);
    cudaGetSymbolAddress((void**)&WT2,  g_WT2);
    cudaGetSymbolAddress((void**)&pL,   g_pL);
    cudaGetSymbolAddress((void**)&pM,   g_pM);

    const int gr8 = BTt / 8;
    dim3 blk(256);

    embed_kernel<<<gr8, blk>>>(item_emb, seq, X);

    // Weight transpose + bf16 convert (tiny)
    for (int l = 0; l < Ll; l++) {
        wt_kernel<<<(Ff * Cc) / 256, 256>>>(fc1_w + (size_t)l * Cc * Ff,
                                            WT1 + (size_t)l * Ff * Cc, Cc, Ff);
        wt_kernel<<<(Cc * Ff) / 256, 256>>>(fc2_w + (size_t)l * Ff * Cc,
                                            WT2 + (size_t)l * Cc * Ff, Ff, Cc);
    }

    for (int l = 0; l < Ll; l++) {
        ln_kernel<<<gr8, blk>>>(X, XLN, nullptr, sln_g, sln_b);
        conv_kernel<<<gr8, blk>>>(XLN, conv_w + (size_t)l * Cc * HK,
                                  conv_b + (size_t)l * HK, Y);
        ln_kernel<<<gr8, blk>>>(Y, XLN, XLNb,
                                ln_g + (size_t)l * Cc, ln_b + (size_t)l * Cc);
        // fc1: [BT,128] @ WT1[512][128] -> Hb bf16 (relu)
        gemm_bf16<Cc, true><<<dim3(Ff / 128, BTt / 128), 256>>>(
            XLNb, WT1 + (size_t)l * Ff * Cc, fc1_b + (size_t)l * Ff,
            nullptr, Hb);
        // fc2: [BT,512] @ WT2[128][512] + bias + res -> X fp32
        gemm_bf16<Ff, false><<<dim3(Cc / 128, BTt / 128), 256>>>(
            Hb, WT2 + (size_t)l * Cc * Ff, fc2_b + (size_t)l * Cc,
            XLN, X);
    }

    ln_kernel<<<gr8, blk>>>(X, XLN, nullptr, sln_g, sln_b);
    loss_kernel<<<gr8, blk>>>(XLN, item_emb, pos, neg, pL, pM);
    reduce_kernel<<<1, 256>>>(pL, pM, (float*)d_out);
}

// round 5
// speedup vs baseline: 1.8885x; 1.0102x over previous
#include <cuda_runtime.h>
#include <cuda_bf16.h>
#include <math.h>
#include <stdint.h>

// Problem constants
#define Tt 200
#define Bb 512
#define Cc 128
#define Hh 4
#define Kk 5
#define Ff 512
#define Ll 2
#define BTt (Tt*Bb)        // 102400 tokens
#define HK  (Hh*Kk)        // 20
#define NPART (BTt/8)

// Scratch
__device__ float g_X  [BTt*Cc];
__device__ float g_XLN[BTt*Cc];
__device__ float g_Y  [BTt*Cc];
__device__ __nv_bfloat16 g_XLNb[BTt*Cc];
__device__ __nv_bfloat16 g_Hb  [BTt*Ff];
__device__ __nv_bfloat16 g_WT1 [Ll*Ff*Cc];
__device__ __nv_bfloat16 g_WT2 [Ll*Cc*Ff];
__device__ float g_pL [NPART];
__device__ float g_pM [NPART];

// ---------------------------------------------------------------------------
__device__ __forceinline__ uint32_t smem_to_u32(const void* p) {
    uint32_t a;
    asm("{ .reg .u64 t; cvta.to.shared.u64 t, %1; cvt.u32.u64 %0, t; }" : "=r"(a) : "l"(p));
    return a;
}
__device__ __forceinline__ void mma_bf16(float* c, const uint32_t* a, const uint32_t* b) {
    asm volatile(
        "mma.sync.aligned.m16n8k16.row.col.f32.bf16.bf16.f32 "
        "{%0,%1,%2,%3}, {%4,%5,%6,%7}, {%8,%9}, {%0,%1,%2,%3};\n"
        : "+f"(c[0]), "+f"(c[1]), "+f"(c[2]), "+f"(c[3])
        : "r"(a[0]), "r"(a[1]), "r"(a[2]), "r"(a[3]), "r"(b[0]), "r"(b[1]));
}
__device__ __forceinline__ void ldsm4(uint32_t* r, uint32_t addr) {
    asm volatile("ldmatrix.sync.aligned.m8n8.x4.shared.b16 {%0,%1,%2,%3}, [%4];"
        : "=r"(r[0]), "=r"(r[1]), "=r"(r[2]), "=r"(r[3]) : "r"(addr));
}
__device__ __forceinline__ void cp16(uint32_t dst, const void* src) {
    asm volatile("cp.async.cg.shared.global [%0], [%1], 16;" :: "r"(dst), "l"(src));
}
#define CP_COMMIT() asm volatile("cp.async.commit_group;" ::: "memory")
#define CP_WAIT3()  asm volatile("cp.async.wait_group 3;" ::: "memory")

// ---------------------------------------------------------------------------
__global__ void embed_kernel(const float* __restrict__ emb,
                             const int* __restrict__ seq,
                             float* __restrict__ X)
{
    int warp = threadIdx.x >> 5, lane = threadIdx.x & 31;
    int p = blockIdx.x * 8 + warp;
    int t = p / Bb, b = p - t * Bb;
    int id = seq[b * Tt + t];
    float4 v = ((const float4*)(emb + (size_t)id * Cc))[lane];
    ((float4*)(X + (size_t)p * Cc))[lane] = v;
}

// ---------------------------------------------------------------------------
__global__ void ln_kernel(const float* __restrict__ in, float* __restrict__ out,
                          __nv_bfloat16* __restrict__ outb,
                          const float* __restrict__ g, const float* __restrict__ beta)
{
    int warp = threadIdx.x >> 5, lane = threadIdx.x & 31;
    int p = blockIdx.x * 8 + warp;
    float4 v = ((const float4*)(in + (size_t)p * Cc))[lane];
    float s = v.x + v.y + v.z + v.w;
    #pragma unroll
    for (int o = 16; o; o >>= 1) s += __shfl_xor_sync(0xffffffffu, s, o);
    float mean = s * (1.0f / Cc);
    float dx = v.x - mean, dy = v.y - mean, dz = v.z - mean, dw = v.w - mean;
    float q = dx*dx + dy*dy + dz*dz + dw*dw;
    #pragma unroll
    for (int o = 16; o; o >>= 1) q += __shfl_xor_sync(0xffffffffu, q, o);
    float rstd = rsqrtf(q * (1.0f / Cc) + 1e-5f);
    float4 gv = ((const float4*)g)[lane];
    float4 bv = ((const float4*)beta)[lane];
    float4 r;
    r.x = dx * rstd * gv.x + bv.x;
    r.y = dy * rstd * gv.y + bv.y;
    r.z = dz * rstd * gv.z + bv.z;
    r.w = dw * rstd * gv.w + bv.w;
    ((float4*)(out + (size_t)p * Cc))[lane] = r;
    if (outb) {
        __nv_bfloat162 h0 = __floats2bfloat162_rn(r.x, r.y);
        __nv_bfloat162 h1 = __floats2bfloat162_rn(r.z, r.w);
        uint2 u;
        u.x = *(uint32_t*)&h0; u.y = *(uint32_t*)&h1;
        *(uint2*)(outb + (size_t)p * Cc + lane * 4) = u;
    }
}

// ---------------------------------------------------------------------------
__global__ void conv_kernel(const float* __restrict__ XLN,
                            const float* __restrict__ cw,
                            const float* __restrict__ cb,
                            float* __restrict__ Y)
{
    int warp = threadIdx.x >> 5, lane = threadIdx.x & 31;
    int p = blockIdx.x * 8 + warp;
    int t = p / Bb, b = p - t * Bb;

    float4 xv = ((const float4*)(XLN + (size_t)p * Cc))[lane];
    int c0 = lane * 4;

    float part[HK];
    #pragma unroll
    for (int j = 0; j < HK; j++) part[j] = 0.0f;
    #pragma unroll
    for (int u = 0; u < 4; u++) {
        float xu = (&xv.x)[u];
        const float* wr = cw + (size_t)(c0 + u) * HK;
        #pragma unroll
        for (int j = 0; j < HK; j++) part[j] += xu * __ldg(wr + j);
    }
    #pragma unroll
    for (int o = 16; o; o >>= 1) {
        #pragma unroll
        for (int j = 0; j < HK; j++)
            part[j] += __shfl_xor_sync(0xffffffffu, part[j], o);
    }

    int h = c0 >> 5;
    float lg[Kk];
    float mx = -1e30f;
    #pragma unroll
    for (int k = 0; k < Kk; k++) {
        lg[k] = part[h * Kk + k] + __ldg(cb + h * Kk + k);
        mx = fmaxf(mx, lg[k]);
    }
    float den = 0.0f;
    #pragma unroll
    for (int k = 0; k < Kk; k++) { lg[k] = expf(lg[k] - mx); den += lg[k]; }
    float inv = 1.0f / den;

    float4 acc = make_float4(0.f, 0.f, 0.f, 0.f);
    #pragma unroll
    for (int k = 0; k < Kk; k++) {
        int ts = t - (Kk - 1) + k;
        if (ts >= 0) {
            float4 wv = ((const float4*)(XLN + ((size_t)ts * Bb + b) * Cc))[lane];
            float wk = lg[k] * inv;
            acc.x += wk * wv.x; acc.y += wk * wv.y;
            acc.z += wk * wv.z; acc.w += wk * wv.w;
        }
    }
    ((float4*)(Y + (size_t)p * Cc))[lane] = acc;
}

// ---------------------------------------------------------------------------
__global__ void wt_kernel(const float* __restrict__ in, __nv_bfloat16* __restrict__ out,
                          int Kd, int Nn)
{
    int idx = blockIdx.x * 256 + threadIdx.x;
    int n = idx / Kd, k = idx - n * Kd;
    out[idx] = __float2bfloat16_rn(in[(size_t)k * Nn + n]);
}

// ---------------------------------------------------------------------------
// bf16 mma.sync GEMM, 5-stage cp.async ring.
// Block 128(M) x 128(N) x 32(K-chunk), 256 threads, 8 warps (4x2).
// Stage layout (16KB): A[128 rows][64B] | B[128 rows][64B], XOR-swizzled 16B chunks.
// ---------------------------------------------------------------------------
#define NSTAGE 5
#define STAGE_BYTES 16384
#define GEMM_SMEM (NSTAGE * STAGE_BYTES)

template<int KD, bool FC1>
__global__ void __launch_bounds__(256, 2)
gemm_bf16(const __nv_bfloat16* __restrict__ A,
          const __nv_bfloat16* __restrict__ Wt,
          const float* __restrict__ bias,
          const float* __restrict__ res,
          void* __restrict__ outp)
{
    extern __shared__ __align__(1024) char sm[];

    const int tid = threadIdx.x;
    const int wid = tid >> 5, lane = tid & 31;
    const int wm = wid & 3, wn = wid >> 2;
    const int bm = blockIdx.y * 128, bn = blockIdx.x * 128;

    const uint32_t sA = smem_to_u32(sm);

    // load mapping: thread handles 16B chunk (row=tid>>2, kb=tid&3) at rows {r, r+64}
    const int arow = tid >> 2, akb = tid & 3;
    const uint32_t loff = arow * 64 + ((akb ^ ((arow >> 1) & 3)) << 4);
    const __nv_bfloat16* pa = A  + (size_t)(bm + arow) * KD + akb * 8;
    const __nv_bfloat16* pb = Wt + (size_t)(bn + arow) * KD + akb * 8;

    // ldmatrix per-lane address components
    const int lgrp = lane >> 3, l7 = lane & 7;
    uint32_t aoff[2]; int axor[2];
    #pragma unroll
    for (int mi = 0; mi < 2; mi++) {
        int r = wm * 32 + mi * 16 + l7 + ((lgrp & 1) << 3);
        aoff[mi] = r * 64; axor[mi] = (r >> 1) & 3;
    }
    const int cA = lgrp >> 1;
    uint32_t boff[4]; int bxor[4];
    #pragma unroll
    for (int nt = 0; nt < 4; nt++) {
        int r = wn * 64 + nt * 16 + l7 + ((lgrp >> 1) << 3);
        boff[nt] = r * 64; bxor[nt] = (r >> 1) & 3;
    }
    const int cB = lgrp & 1;

    float acc[2][8][4];
    #pragma unroll
    for (int mi = 0; mi < 2; mi++)
        #pragma unroll
        for (int ni = 0; ni < 8; ni++)
            #pragma unroll
            for (int q = 0; q < 4; q++) acc[mi][ni][q] = 0.0f;

    const int NIT = KD / 32;

    // prologue: issue NSTAGE-1 (or NIT) stages
    #pragma unroll
    for (int s = 0; s < NSTAGE - 1; s++) {
        if (s < NIT) {
            uint32_t dA = sA + s * STAGE_BYTES + loff;
            const __nv_bfloat16* qa = pa + s * 32;
            const __nv_bfloat16* qb = pb + s * 32;
            cp16(dA,         qa);
            cp16(dA + 4096,  qa + (size_t)64 * KD);
            cp16(dA + 8192,  qb);
            cp16(dA + 12288, qb + (size_t)64 * KD);
        }
        CP_COMMIT();
    }

    for (int it = 0; it < NIT; it++) {
        CP_WAIT3();          // stage `it` complete (4 groups max in flight)
        __syncthreads();     // all warps see data; all warps past compute(it-1)

        // issue stage it+NSTAGE-1 into buffer (it-1)%NSTAGE — free after the sync
        {
            int s = it + NSTAGE - 1;
            if (s < NIT) {
                uint32_t dA = sA + (s % NSTAGE) * STAGE_BYTES + loff;
                const __nv_bfloat16* qa = pa + s * 32;
                const __nv_bfloat16* qb = pb + s * 32;
                cp16(dA,         qa);
                cp16(dA + 4096,  qa + (size_t)64 * KD);
                cp16(dA + 8192,  qb);
                cp16(dA + 12288, qb + (size_t)64 * KD);
            }
            CP_COMMIT();     // empty groups at tail keep the accounting exact
        }

        const uint32_t bufA = sA + (it % NSTAGE) * STAGE_BYTES;
        const uint32_t bufB = bufA + 8192;

        #pragma unroll
        for (int s = 0; s < 2; s++) {
            uint32_t af[2][4], bf[4][4];
            #pragma unroll
            for (int mi = 0; mi < 2; mi++)
                ldsm4(af[mi], bufA + aoff[mi] + (((2 * s + cA) ^ axor[mi]) << 4));
            #pragma unroll
            for (int nt = 0; nt < 4; nt++)
                ldsm4(bf[nt], bufB + boff[nt] + (((2 * s + cB) ^ bxor[nt]) << 4));
            #pragma unroll
            for (int mi = 0; mi < 2; mi++)
                #pragma unroll
                for (int ni = 0; ni < 8; ni++)
                    mma_bf16(acc[mi][ni], af[mi], &bf[ni >> 1][(ni & 1) * 2]);
        }
    }

    // epilogue
    const int g = lane >> 2, i4 = lane & 3;
    #pragma unroll
    for (int mi = 0; mi < 2; mi++) {
        int r0 = bm + wm * 32 + mi * 16 + g;
        #pragma unroll
        for (int ni = 0; ni < 8; ni++) {
            int col = bn + wn * 64 + ni * 8 + i4 * 2;
            float b0 = __ldg(bias + col), b1 = __ldg(bias + col + 1);
            float v0 = acc[mi][ni][0] + b0, v1 = acc[mi][ni][1] + b1;
            float v2 = acc[mi][ni][2] + b0, v3 = acc[mi][ni][3] + b1;
            if (FC1) {
                v0 = fmaxf(v0, 0.f); v1 = fmaxf(v1, 0.f);
                v2 = fmaxf(v2, 0.f); v3 = fmaxf(v3, 0.f);
                __nv_bfloat16* O = (__nv_bfloat16*)outp;
                *(__nv_bfloat162*)(O + (size_t)r0 * Ff + col) =
                    __floats2bfloat162_rn(v0, v1);
                *(__nv_bfloat162*)(O + (size_t)(r0 + 8) * Ff + col) =
                    __floats2bfloat162_rn(v2, v3);
            } else {
                float* O = (float*)outp;
                float2 rv0 = *(const float2*)(res + (size_t)r0 * Cc + col);
                float2 rv1 = *(const float2*)(res + (size_t)(r0 + 8) * Cc + col);
                *(float2*)(O + (size_t)r0 * Cc + col) =
                    make_float2(v0 + rv0.x, v1 + rv0.y);
                *(float2*)(O + (size_t)(r0 + 8) * Cc + col) =
                    make_float2(v2 + rv1.x, v3 + rv1.y);
            }
        }
    }
}

// ---------------------------------------------------------------------------
__global__ void loss_kernel(const float* __restrict__ se,
                            const float* __restrict__ emb,
                            const int* __restrict__ pos,
                            const int* __restrict__ neg,
                            float* __restrict__ pL, float* __restrict__ pM)
{
    int warp = threadIdx.x >> 5, lane = threadIdx.x & 31;
    int i = blockIdx.x * 8 + warp;
    int b = i / Tt, t = i - b * Tt;
    int p = t * Bb + b;

    float4 e  = ((const float4*)(se  + (size_t)p   * Cc))[lane];
    int pid = pos[i];
    int nid = neg[i];
    float4 pv = ((const float4*)(emb + (size_t)pid * Cc))[lane];
    float4 nv = ((const float4*)(emb + (size_t)nid * Cc))[lane];
    float dp = e.x*pv.x + e.y*pv.y + e.z*pv.z + e.w*pv.w;
    float dn = e.x*nv.x + e.y*nv.y + e.z*nv.z + e.w*nv.w;
    #pragma unroll
    for (int o = 16; o; o >>= 1) {
        dp += __shfl_xor_sync(0xffffffffu, dp, o);
        dn += __shfl_xor_sync(0xffffffffu, dn, o);
    }

    __shared__ float sL[8], sM[8];
    if (lane == 0) {
        float sp = 1.0f / (1.0f + expf(-dp));
        float sn = 1.0f / (1.0f + expf(-dn));
        float val = -logf(sp + 1e-24f) - logf(1.0f - sn + 1e-24f);
        float m = (pid != 0) ? 1.0f : 0.0f;
        sL[warp] = val * m;
        sM[warp] = m;
    }
    __syncthreads();
    if (threadIdx.x == 0) {
        float a = 0.f, mm = 0.f;
        #pragma unroll
        for (int w = 0; w < 8; w++) { a += sL[w]; mm += sM[w]; }
        pL[blockIdx.x] = a;
        pM[blockIdx.x] = mm;
    }
}

__global__ void reduce_kernel(const float* __restrict__ pL,
                              const float* __restrict__ pM,
                              float* __restrict__ out)
{
    __shared__ double sL[256], sM[256];
    double a = 0.0, m = 0.0;
    for (int i = threadIdx.x; i < NPART; i += 256) { a += pL[i]; m += pM[i]; }
    sL[threadIdx.x] = a; sM[threadIdx.x] = m;
    __syncthreads();
    for (int s = 128; s; s >>= 1) {
        if (threadIdx.x < s) {
            sL[threadIdx.x] += sL[threadIdx.x + s];
            sM[threadIdx.x] += sM[threadIdx.x + s];
        }
        __syncthreads();
    }
    if (threadIdx.x == 0) out[0] = (float)(sL[0] / sM[0]);
}

// ---------------------------------------------------------------------------
extern "C" void kernel_launch(void* const* d_in, const int* in_sizes, int n_in,
                              void* d_out, int out_size)
{
    const float* item_emb = (const float*)d_in[0];
    const float* conv_w   = (const float*)d_in[1];
    const float* conv_b   = (const float*)d_in[2];
    const float* ln_g     = (const float*)d_in[3];
    const float* ln_b     = (const float*)d_in[4];
    const float* fc1_w    = (const float*)d_in[5];
    const float* fc1_b    = (const float*)d_in[6];
    const float* fc2_w    = (const float*)d_in[7];
    const float* fc2_b    = (const float*)d_in[8];
    const float* sln_g    = (const float*)d_in[9];
    const float* sln_b    = (const float*)d_in[10];
    const int*   seq      = (const int*)d_in[11];
    const int*   pos      = (const int*)d_in[12];
    const int*   neg      = (const int*)d_in[13];

    float *X, *XLN, *Y, *pL, *pM;
    __nv_bfloat16 *XLNb, *Hb, *WT1, *WT2;
    cudaGetSymbolAddress((void**)&X,    g_X);
    cudaGetSymbolAddress((void**)&XLN,  g_XLN);
    cudaGetSymbolAddress((void**)&Y,    g_Y);
    cudaGetSymbolAddress((void**)&XLNb, g_XLNb);
    cudaGetSymbolAddress((void**)&Hb,   g_Hb);
    cudaGetSymbolAddress((void**)&WT1,  g_WT1);
    cudaGetSymbolAddress((void**)&WT2,  g_WT2);
    cudaGetSymbolAddress((void**)&pL,   g_pL);
    cudaGetSymbolAddress((void**)&pM,   g_pM);

    cudaFuncSetAttribute(gemm_bf16<Cc, true>,
        cudaFuncAttributeMaxDynamicSharedMemorySize, GEMM_SMEM);
    cudaFuncSetAttribute(gemm_bf16<Ff, false>,
        cudaFuncAttributeMaxDynamicSharedMemorySize, GEMM_SMEM);

    const int gr8 = BTt / 8;
    dim3 blk(256);

    embed_kernel<<<gr8, blk>>>(item_emb, seq, X);

    for (int l = 0; l < Ll; l++) {
        wt_kernel<<<(Ff * Cc) / 256, 256>>>(fc1_w + (size_t)l * Cc * Ff,
                                            WT1 + (size_t)l * Ff * Cc, Cc, Ff);
        wt_kernel<<<(Cc * Ff) / 256, 256>>>(fc2_w + (size_t)l * Ff * Cc,
                                            WT2 + (size_t)l * Cc * Ff, Ff, Cc);
    }

    for (int l = 0; l < Ll; l++) {
        ln_kernel<<<gr8, blk>>>(X, XLN, nullptr, sln_g, sln_b);
        conv_kernel<<<gr8, blk>>>(XLN, conv_w + (size_t)l * Cc * HK,
                                  conv_b + (size_t)l * HK, Y);
        ln_kernel<<<gr8, blk>>>(Y, XLN, XLNb,
                                ln_g + (size_t)l * Cc, ln_b + (size_t)l * Cc);
        gemm_bf16<Cc, true><<<dim3(Ff / 128, BTt / 128), 256, GEMM_SMEM>>>(
            XLNb, WT1 + (size_t)l * Ff * Cc, fc1_b + (size_t)l * Ff,
            nullptr, Hb);
        gemm_bf16<Ff, false><<<dim3(Cc / 128, BTt / 128), 256, GEMM_SMEM>>>(
            Hb, WT2 + (size_t)l * Cc * Ff, fc2_b + (size_t)l * Cc,
            XLN, X);
    }

    ln_kernel<<<gr8, blk>>>(X, XLN, nullptr, sln_g, sln_b);
    loss_kernel<<<gr8, blk>>>(XLN, item_emb, pos, neg, pL, pM);
    reduce_kernel<<<1, 256>>>(pL, pM, (float*)d_out);
}